// round 13
// baseline (speedup 1.0000x reference)
#include <cuda_runtime.h>

// SplineLoss on GB300: reference samples the spline only at integer knot
// times (t = 0,10,...,1020) where dx == 0.0 exactly, so all moment terms
// vanish: loss == mean over s,b,d of (true[b,10s,d]-pred[b,10s,d])^2.
//
// R13 = R12 champion with finer tail granularity: 1648 blocks x 128 thr
// (same 210944 threads, one float4-pair each, single wave), 16 bins
// (103 atomics/address — same contention as champion). Block tail combines
// 4 warp partials instead of 8; BAR drain cheaper; CTA retire more parallel.
// Epilogue keeps the R12 reorder (fold ATOMG before bin-reset STG).

#define T_ 1024
#define D4_ 16                   // 64 floats per row = 16 float4
#define S_ 103                   // sample times 0,10,...,1020
#define ROW_STRIDE4_ (T_ * D4_)  // float4 stride between batches
#define COUNT_ 843776.0          // 128 * 103 * 64
#define FIX_SCALE 16777216.0     // 2^24

constexpr int NBLK  = 16 * S_;   // 1648 blocks, 16 per sample time
constexpr int NTHR  = 128;       // 8 batches x 16 float4
constexpr int NBINS = 16;
constexpr int BINSZ = NBLK / NBINS;   // 103

__device__ __align__(256) unsigned long long g_bins[NBINS * 32]; // use [i*32]
__device__ __align__(256) unsigned long long g_final = 0;

__global__ __launch_bounds__(NTHR) void spline_mse_r13(
    const float* __restrict__ yt, const float* __restrict__ yp,
    float* __restrict__ out)
{
    const int s = blockIdx.x >> 4;             // 0..102
    const int q = blockIdx.x & 15;             // batch group [8q, 8q+8)
    const int d4   = threadIdx.x & (D4_ - 1);
    const int brel = threadIdx.x >> 4;         // 0..7

    const int addr = s * 10 * D4_ + (q * 8 + brel) * ROW_STRIDE4_ + d4;
    const float4 va = __ldg((const float4*)yt + addr);
    const float4 vb = __ldg((const float4*)yp + addr);

    float e0 = va.x - vb.x;
    float e1 = va.y - vb.y;
    float e2 = va.z - vb.z;
    float e3 = va.w - vb.w;
    float acc = e0 * e0;
    acc = fmaf(e1, e1, acc);
    acc = fmaf(e2, e2, acc);
    acc = fmaf(e3, e3, acc);

    // warp reduce (fixed order -> deterministic)
    #pragma unroll
    for (int o = 16; o > 0; o >>= 1)
        acc += __shfl_down_sync(0xffffffffu, acc, o);

    __shared__ float sh[NTHR / 32];
    if ((threadIdx.x & 31) == 0) sh[threadIdx.x >> 5] = acc;
    __syncthreads();

    if (threadIdx.x != 0) return;              // thread 0 only past here

    float v = (sh[0] + sh[1]) + (sh[2] + sh[3]);   // 4 warp partials

    // level 1: bin atomic (103 blocks per address, 16 addresses parallel)
    unsigned long long fixed =
        __double2ull_rn((double)v * FIX_SCALE);          // v >= 0, exact int
    unsigned long long* bin = &g_bins[(blockIdx.x & (NBINS - 1)) * 32];
    unsigned long long old = atomicAdd(bin, (fixed << 16) | 1ull);

    if ((old & 0xFFFFull) != (unsigned long long)(BINSZ - 1)) return;

    // bin-last: fold FIRST (critical ATOMG), then reset bin in its shadow
    unsigned long long bin_total = (old >> 16) + fixed;
    unsigned long long fold = atomicAdd(&g_final, (bin_total << 16) | 1ull);
    *bin = 0ull;                                         // next-replay reset

    if ((fold & 0xFFFFull) == (unsigned long long)(NBINS - 1)) {
        unsigned long long total = (fold >> 16) + bin_total;
        out[0] = (float)((double)total / (FIX_SCALE * COUNT_));
        g_final = 0ull;                                  // reset for replay
    }
}

extern "C" void kernel_launch(void* const* d_in, const int* in_sizes, int n_in,
                              void* d_out, int out_size)
{
    const float* yt = (const float*)d_in[0];   // true_frames
    const float* yp = (const float*)d_in[1];   // predicted_frames
    spline_mse_r13<<<NBLK, NTHR>>>(yt, yp, (float*)d_out);
}

// round 14
// speedup vs baseline: 1.0047x; 1.0047x over previous
#include <cuda_runtime.h>

// SplineLoss on GB300: reference samples the spline only at integer knot
// times (t = 0,10,...,1020) where dx == 0.0 exactly, so all moment terms
// vanish: loss == mean over s,b,d of (true[b,10s,d]-pred[b,10s,d])^2.
//
// R14 = R12 champion (824x256 single wave, SHFL trees, 8-bin two-level
// deterministic fixed-point atomic tail, fold-before-reset epilogue) with
// two tail micro-cuts:
//  - fp32 fixed-point conversion (FMUL+F2I ~24cy) instead of the f64 chain
//    (F2F.F64+DMUL+D2I ~60+cy; FP64 is slow on B300). rel err ~1e-7.
//  - pairwise combine of the 8 warp partials (3 dependent adds, not 7).
// Mapped-out search space: grid{103..1648} x block{128,256,512} x
// tail{fence,1-level,2-level,warp-atomic} x reduce{SHFL,REDUX}; this
// configuration is the measured optimum.

#define T_ 1024
#define D4_ 16                   // 64 floats per row = 16 float4
#define S_ 103                   // sample times 0,10,...,1020
#define ROW_STRIDE4_ (T_ * D4_)  // float4 stride between batches
#define COUNT_ 843776.0          // 128 * 103 * 64
#define FIX_SCALE 16777216.0     // 2^24

constexpr int NBLK  = 8 * S_;    // 824 blocks, 8 per sample time
constexpr int NTHR  = 256;       // 16 batches x 16 float4
constexpr int NBINS = 8;
constexpr int BINSZ = NBLK / NBINS;   // 103

__device__ __align__(256) unsigned long long g_bins[NBINS * 32]; // use [i*32]
__device__ __align__(256) unsigned long long g_final = 0;

__global__ __launch_bounds__(NTHR) void spline_mse_r14(
    const float* __restrict__ yt, const float* __restrict__ yp,
    float* __restrict__ out)
{
    const int s = blockIdx.x >> 3;             // 0..102
    const int q = blockIdx.x & 7;              // batch group [16q, 16q+16)
    const int d4   = threadIdx.x & (D4_ - 1);
    const int brel = threadIdx.x >> 4;         // 0..15

    const int addr = s * 10 * D4_ + (q * 16 + brel) * ROW_STRIDE4_ + d4;
    const float4 va = __ldg((const float4*)yt + addr);
    const float4 vb = __ldg((const float4*)yp + addr);

    float e0 = va.x - vb.x;
    float e1 = va.y - vb.y;
    float e2 = va.z - vb.z;
    float e3 = va.w - vb.w;
    float acc = e0 * e0;
    acc = fmaf(e1, e1, acc);
    acc = fmaf(e2, e2, acc);
    acc = fmaf(e3, e3, acc);

    // warp reduce (fixed order -> deterministic)
    #pragma unroll
    for (int o = 16; o > 0; o >>= 1)
        acc += __shfl_down_sync(0xffffffffu, acc, o);

    __shared__ float sh[NTHR / 32];
    if ((threadIdx.x & 31) == 0) sh[threadIdx.x >> 5] = acc;
    __syncthreads();

    if (threadIdx.x != 0) return;              // thread 0 only past here

    // pairwise combine: 3 dependent adds instead of 7
    float v = ((sh[0] + sh[1]) + (sh[2] + sh[3]))
            + ((sh[4] + sh[5]) + (sh[6] + sh[7]));

    // fp32 fixed-point (deterministic; quantization rel err ~1e-7)
    unsigned long long fixed = __float2ull_rn(v * (float)FIX_SCALE);

    // level 1: bin atomic (103 blocks per address, 8 addresses in parallel)
    unsigned long long* bin = &g_bins[(blockIdx.x & (NBINS - 1)) * 32];
    unsigned long long old = atomicAdd(bin, (fixed << 16) | 1ull);

    if ((old & 0xFFFFull) != (unsigned long long)(BINSZ - 1)) return;

    // bin-last: fold FIRST (critical ATOMG), then reset bin in its shadow
    unsigned long long bin_total = (old >> 16) + fixed;
    unsigned long long fold = atomicAdd(&g_final, (bin_total << 16) | 1ull);
    *bin = 0ull;                                         // next-replay reset

    if ((fold & 0xFFFFull) == (unsigned long long)(NBINS - 1)) {
        unsigned long long total = (fold >> 16) + bin_total;
        out[0] = (float)((double)total / (FIX_SCALE * COUNT_));
        g_final = 0ull;                                  // reset for replay
    }
}

extern "C" void kernel_launch(void* const* d_in, const int* in_sizes, int n_in,
                              void* d_out, int out_size)
{
    const float* yt = (const float*)d_in[0];   // true_frames
    const float* yp = (const float*)d_in[1];   // predicted_frames
    spline_mse_r14<<<NBLK, NTHR>>>(yt, yp, (float*)d_out);
}